// round 5
// baseline (speedup 1.0000x reference)
#include <cuda_runtime.h>
#include <stdint.h>

#define BATCH 64
#define NPTS  131072
#define MPTS  2048
#define TILE  2048                 // points per block in k_mask_stats
#define NTILE (NPTS / TILE)        // 64 tiles per batch
#define NWORDS (NPTS / 32)         // 4096 mask words per batch

// ---- scratch (device globals; no runtime allocation) ----
__device__ __align__(16) unsigned g_maskbits[BATCH * NWORDS];   // 1 bit per point
__device__ int      g_wordpref[BATCH * NWORDS];                 // exclusive popc prefix per word
__device__ float    g_blocksum[BATCH * NTILE * 3];              // per-tile masked xyz sums
__device__ int      g_cnt[BATCH];
__device__ float    g_mean[BATCH * 3];
__device__ uint32_t g_hi[BATCH * MPTS];                         // precomputed threefry draws
__device__ uint32_t g_lo[BATCH * MPTS];

// ---------------- Threefry-2x32 (matches JAX exactly) ----------------
__host__ __device__ inline void threefry2x32(uint32_t k0, uint32_t k1,
                                             uint32_t c0, uint32_t c1,
                                             uint32_t& o0, uint32_t& o1) {
    uint32_t ks2 = k0 ^ k1 ^ 0x1BD11BDAu;
    uint32_t x0 = c0 + k0, x1 = c1 + k1;
#define TF_ROUND(r) { x0 += x1; x1 = (x1 << (r)) | (x1 >> (32 - (r))); x1 ^= x0; }
    TF_ROUND(13) TF_ROUND(15) TF_ROUND(26) TF_ROUND(6)
    x0 += k1;  x1 += ks2 + 1u;
    TF_ROUND(17) TF_ROUND(29) TF_ROUND(16) TF_ROUND(24)
    x0 += ks2; x1 += k0 + 2u;
    TF_ROUND(13) TF_ROUND(15) TF_ROUND(26) TF_ROUND(6)
    x0 += k0;  x1 += k1 + 3u;
    TF_ROUND(17) TF_ROUND(29) TF_ROUND(16) TF_ROUND(24)
    x0 += k1;  x1 += ks2 + 4u;
    TF_ROUND(13) TF_ROUND(15) TF_ROUND(26) TF_ROUND(6)
    x0 += ks2; x1 += k0 + 5u;
#undef TF_ROUND
    o0 = x0; o1 = x1;
}

// ---------------- Kernel 1: mask bits + per-tile masked-xyz sums + threefry precompute ----------
__global__ void __launch_bounds__(256)
k_mask_stats(const float* __restrict__ pc, const float* __restrict__ logits,
             uint32_t k1a, uint32_t k1b, uint32_t k2a, uint32_t k2b) {
    const int tile = blockIdx.x;             // 0..NTILE-1
    const int b    = blockIdx.y;             // 0..BATCH-1
    const int lane = threadIdx.x & 31, warp = threadIdx.x >> 5;

    const float*  l0 = logits + (size_t)b * 2 * NPTS;
    const float*  l1 = l0 + NPTS;
    const float4* p4 = (const float4*)pc + (size_t)b * NPTS;

    const int wbase = tile * TILE + warp * 256;   // this warp's 256 points
    float sx = 0.f, sy = 0.f, sz = 0.f;

    #pragma unroll
    for (int k = 0; k < 8; ++k) {
        const int n = wbase + k * 32 + lane;
        const bool m = __ldg(&l0[n]) < __ldg(&l1[n]);
        const unsigned bal = __ballot_sync(0xffffffffu, m);
        const float4 p = __ldg(&p4[n]);
        if (lane == 0)
            g_maskbits[(size_t)b * NWORDS + (unsigned)(wbase + k * 32) / 32] = bal;
        if (m) { sx += p.x; sy += p.y; sz += p.z; }
    }

    // Free ALU under the memory shadow: warp 0 computes this block's 32
    // threefry draws for the selection kernel (slot = b*MPTS + tile*32 + lane).
    if (warp == 0) {
        const uint32_t slot = (uint32_t)(b * MPTS + tile * 32 + lane);
        uint32_t h0, h1, q0, q1;
        threefry2x32(k1a, k1b, 0u, slot, h0, h1);
        threefry2x32(k2a, k2b, 0u, slot, q0, q1);
        g_hi[slot] = h0 ^ h1;
        g_lo[slot] = q0 ^ q1;
    }

    #pragma unroll
    for (int o = 16; o; o >>= 1) {
        sx += __shfl_down_sync(0xffffffffu, sx, o);
        sy += __shfl_down_sync(0xffffffffu, sy, o);
        sz += __shfl_down_sync(0xffffffffu, sz, o);
    }
    __shared__ float ss[8][3];
    if (lane == 0) { ss[warp][0] = sx; ss[warp][1] = sy; ss[warp][2] = sz; }
    __syncthreads();
    if (warp == 0 && lane < 8) {
        sx = ss[lane][0]; sy = ss[lane][1]; sz = ss[lane][2];
        #pragma unroll
        for (int o = 4; o; o >>= 1) {
            sx += __shfl_down_sync(0x000000ffu, sx, o);
            sy += __shfl_down_sync(0x000000ffu, sy, o);
            sz += __shfl_down_sync(0x000000ffu, sz, o);
        }
        if (lane == 0) {
            const int idx = b * NTILE + tile;
            g_blocksum[idx * 3 + 0] = sx;
            g_blocksum[idx * 3 + 1] = sy;
            g_blocksum[idx * 3 + 2] = sz;
        }
    }
}

// ---------------- Kernel 2: per-batch word-popcount prefix + cnt + mean ----------------
__global__ void __launch_bounds__(512)
k_prefix(float* __restrict__ out_mean, int has_mean) {
    const int b = blockIdx.x;                 // one block per batch
    const int t = threadIdx.x;                // 512 threads, 8 words each
    const int lane = t & 31, warp = t >> 5;   // 16 warps

    const uint4* mb4 = (const uint4*)(g_maskbits + (size_t)b * NWORDS);
    uint4 a0 = __ldg(&mb4[t * 2 + 0]);
    uint4 a1 = __ldg(&mb4[t * 2 + 1]);

    int c[8];
    c[0] = __popc(a0.x); c[1] = __popc(a0.y); c[2] = __popc(a0.z); c[3] = __popc(a0.w);
    c[4] = __popc(a1.x); c[5] = __popc(a1.y); c[6] = __popc(a1.z); c[7] = __popc(a1.w);

    int lp[8]; int s = 0;
    #pragma unroll
    for (int i = 0; i < 8; ++i) { lp[i] = s; s += c[i]; }

    int inc = s;
    #pragma unroll
    for (int o = 1; o < 32; o <<= 1) {
        int v = __shfl_up_sync(0xffffffffu, inc, o);
        if (lane >= o) inc += v;
    }
    __shared__ int swarp[16], swpref[16], stot;
    if (lane == 31) swarp[warp] = inc;
    __syncthreads();
    if (warp == 0 && lane < 16) {
        int v = swarp[lane], winc = v;
        #pragma unroll
        for (int o = 1; o < 16; o <<= 1) {
            int u = __shfl_up_sync(0x0000ffffu, winc, o);
            if (lane >= o) winc += u;
        }
        swpref[lane] = winc - v;
        if (lane == 15) stot = winc;
    }
    __syncthreads();

    const int off = swpref[warp] + (inc - s);
    int* __restrict__ pref = g_wordpref + (size_t)b * NWORDS + t * 8;
    #pragma unroll
    for (int i = 0; i < 8; ++i) pref[i] = off + lp[i];

    const int tot = stot;
    if (t == 0) g_cnt[b] = tot;

    if (warp == 1) {
        const int i0 = (b * NTILE + lane) * 3;
        const int i1 = (b * NTILE + lane + 32) * 3;
        float sx = g_blocksum[i0 + 0] + g_blocksum[i1 + 0];
        float sy = g_blocksum[i0 + 1] + g_blocksum[i1 + 1];
        float sz = g_blocksum[i0 + 2] + g_blocksum[i1 + 2];
        #pragma unroll
        for (int o = 16; o; o >>= 1) {
            sx += __shfl_down_sync(0xffffffffu, sx, o);
            sy += __shfl_down_sync(0xffffffffu, sy, o);
            sz += __shfl_down_sync(0xffffffffu, sz, o);
        }
        if (lane == 0) {
            const float d = fmaxf((float)tot, 1.0f);
            const float mx = sx / d, my = sy / d, mz = sz / d;
            g_mean[b * 3 + 0] = mx; g_mean[b * 3 + 1] = my; g_mean[b * 3 + 2] = mz;
            if (has_mean) {
                out_mean[b * 3 + 0] = mx;
                out_mean[b * 3 + 1] = my;
                out_mean[b * 3 + 2] = mz;
            }
        }
    }
}

// ---------------- Kernel 3: selection, full-chip parallel (1 thread = 1 output point) --------
__global__ void __launch_bounds__(256)
k_select(const float* __restrict__ pc, float* __restrict__ out) {
    const int b = blockIdx.y;
    const int j = blockIdx.x * 256 + threadIdx.x;   // 0..MPTS-1
    const int slot = b * MPTS + j;

    // issue independent loads up front
    const int cnt = __ldg(&g_cnt[b]);
    const uint32_t higher = __ldg(&g_hi[slot]);
    const uint32_t lower  = __ldg(&g_lo[slot]);
    const float mx = __ldg(&g_mean[b * 3 + 0]);
    const float my = __ldg(&g_mean[b * 3 + 1]);
    const float mz = __ldg(&g_mean[b * 3 + 2]);

    float* __restrict__ o = out + (size_t)slot * 3;

    if (cnt == 0) {                          // empty-mask override: batch id
        const float v = (float)b;
        o[0] = v; o[1] = v; o[2] = v;
        return;
    }

    const uint32_t span = (uint32_t)cnt;
    uint32_t mult = 65536u % span;
    mult = (mult * mult) % span;             // uint32 wraparound — matches lax semantics
    const int rnd = (int)(((higher % span) * mult + (lower % span)) % span);
    const int sel = (cnt <= MPTS && j < cnt) ? j : rnd;

    // binary search: largest word w with pref[w] <= sel (pref exclusive, pref[0]=0)
    const int* __restrict__ pref = g_wordpref + (size_t)b * NWORDS;
    int lo = 0, hi = NWORDS, plo = 0;
    #pragma unroll
    for (int st = 0; st < 12; ++st) {        // 2^12 = 4096
        const int mid = (lo + hi) >> 1;
        const int v = __ldg(&pref[mid]);
        const bool le = (v <= sel);
        lo  = le ? mid : lo;
        plo = le ? v   : plo;
        hi  = le ? hi  : mid;
    }
    unsigned w = __ldg(&g_maskbits[(size_t)b * NWORDS + lo]);
    int r = sel - plo;                       // r-th set bit of w (0-based)

    int p = 0;
    {
        int cc = __popc(w & 0xFFFFu); if (r >= cc) { r -= cc; p += 16; w >>= 16; }
        cc = __popc(w & 0xFFu);       if (r >= cc) { r -= cc; p += 8;  w >>= 8;  }
        cc = __popc(w & 0xFu);        if (r >= cc) { r -= cc; p += 4;  w >>= 4;  }
        cc = __popc(w & 0x3u);        if (r >= cc) { r -= cc; p += 2;  w >>= 2;  }
        cc = (int)(w & 1u);           if (r >= cc) {          p += 1;            }
    }
    const int idx = lo * 32 + p;

    const float4 pt = __ldg((const float4*)pc + (size_t)b * NPTS + idx);
    o[0] = pt.x - mx;
    o[1] = pt.y - my;
    o[2] = pt.z - mz;
}

// ---------------- launch ----------------
extern "C" void kernel_launch(void* const* d_in, const int* in_sizes, int n_in,
                              void* d_out, int out_size) {
    const float* pc     = (const float*)d_in[0];
    const float* logits = (const float*)d_in[1];
    if (n_in >= 2 && in_sizes[0] == BATCH * 2 * NPTS && in_sizes[1] == BATCH * NPTS * 4) {
        pc     = (const float*)d_in[1];
        logits = (const float*)d_in[0];
    }
    float* out = (float*)d_out;

    // split(key(42)) — partitionable/foldlike: counters (0,0) and (0,1)
    uint32_t k1a, k1b, k2a, k2b;
    threefry2x32(0u, 42u, 0u, 0u, k1a, k1b);
    threefry2x32(0u, 42u, 0u, 1u, k2a, k2b);

    const size_t obj_elems = (size_t)BATCH * MPTS * 3;
    const int has_mean = (out_size >= (int)(obj_elems + BATCH * 3)) ? 1 : 0;

    k_mask_stats<<<dim3(NTILE, BATCH), 256>>>(pc, logits, k1a, k1b, k2a, k2b);
    k_prefix    <<<BATCH, 512>>>(out + obj_elems, has_mean);
    k_select    <<<dim3(MPTS / 256, BATCH), 256>>>(pc, out);
}

// round 6
// speedup vs baseline: 1.0499x; 1.0499x over previous
#include <cuda_runtime.h>
#include <stdint.h>

#define BATCH 64
#define NPTS  131072
#define MPTS  2048
#define TILE  2048                 // points per block in k_mask_stats
#define NTILE (NPTS / TILE)        // 64 tiles per batch
#define NWORDS (NPTS / 32)         // 4096 mask words per batch

// ---- scratch (device globals; no runtime allocation; zero-initialized) ----
__device__ __align__(16) unsigned g_maskbits[BATCH * NWORDS];   // 1 bit per point
__device__ __align__(16) int g_wordpref[BATCH * NWORDS];        // exclusive popc prefix per word
__device__ float    g_blocksum[BATCH * NTILE * 3];              // per-tile masked xyz sums
__device__ int      g_cnt[BATCH];
__device__ float    g_mean[BATCH * 3];
__device__ uint32_t g_hi[BATCH * MPTS];                         // precomputed threefry draws
__device__ uint32_t g_lo[BATCH * MPTS];
__device__ int      g_arrive[BATCH];                            // per-batch arrival counters

// ---------------- Threefry-2x32 (matches JAX exactly) ----------------
__host__ __device__ inline void threefry2x32(uint32_t k0, uint32_t k1,
                                             uint32_t c0, uint32_t c1,
                                             uint32_t& o0, uint32_t& o1) {
    uint32_t ks2 = k0 ^ k1 ^ 0x1BD11BDAu;
    uint32_t x0 = c0 + k0, x1 = c1 + k1;
#define TF_ROUND(r) { x0 += x1; x1 = (x1 << (r)) | (x1 >> (32 - (r))); x1 ^= x0; }
    TF_ROUND(13) TF_ROUND(15) TF_ROUND(26) TF_ROUND(6)
    x0 += k1;  x1 += ks2 + 1u;
    TF_ROUND(17) TF_ROUND(29) TF_ROUND(16) TF_ROUND(24)
    x0 += ks2; x1 += k0 + 2u;
    TF_ROUND(13) TF_ROUND(15) TF_ROUND(26) TF_ROUND(6)
    x0 += k0;  x1 += k1 + 3u;
    TF_ROUND(17) TF_ROUND(29) TF_ROUND(16) TF_ROUND(24)
    x0 += k1;  x1 += ks2 + 4u;
    TF_ROUND(13) TF_ROUND(15) TF_ROUND(26) TF_ROUND(6)
    x0 += ks2; x1 += k0 + 5u;
#undef TF_ROUND
    o0 = x0; o1 = x1;
}

// ---------------- Kernel 1: mask + sums + threefry; last block per batch builds prefix ------
__global__ void __launch_bounds__(256)
k_mask_stats(const float* __restrict__ pc, const float* __restrict__ logits,
             uint32_t k1a, uint32_t k1b, uint32_t k2a, uint32_t k2b,
             float* __restrict__ out_mean, int has_mean) {
    const int tile = blockIdx.x;             // 0..NTILE-1
    const int b    = blockIdx.y;             // 0..BATCH-1
    const int t    = threadIdx.x;
    const int lane = t & 31, warp = t >> 5;

    const float*  l0 = logits + (size_t)b * 2 * NPTS;
    const float*  l1 = l0 + NPTS;
    const float4* p4 = (const float4*)pc + (size_t)b * NPTS;

    const int wbase = tile * TILE + warp * 256;   // this warp's 256 points
    float sx = 0.f, sy = 0.f, sz = 0.f;

    #pragma unroll
    for (int k = 0; k < 8; ++k) {
        const int n = wbase + k * 32 + lane;
        const bool m = __ldg(&l0[n]) < __ldg(&l1[n]);
        const unsigned bal = __ballot_sync(0xffffffffu, m);
        const float4 p = __ldg(&p4[n]);
        if (lane == 0)
            g_maskbits[(size_t)b * NWORDS + (unsigned)(wbase + k * 32) / 32] = bal;
        if (m) { sx += p.x; sy += p.y; sz += p.z; }
    }

    // free ALU under the memory shadow: threefry draws for selection
    if (warp == 0) {
        const uint32_t slot = (uint32_t)(b * MPTS + tile * 32 + lane);
        uint32_t h0, h1, q0, q1;
        threefry2x32(k1a, k1b, 0u, slot, h0, h1);
        threefry2x32(k2a, k2b, 0u, slot, q0, q1);
        g_hi[slot] = h0 ^ h1;
        g_lo[slot] = q0 ^ q1;
    }

    #pragma unroll
    for (int o = 16; o; o >>= 1) {
        sx += __shfl_down_sync(0xffffffffu, sx, o);
        sy += __shfl_down_sync(0xffffffffu, sy, o);
        sz += __shfl_down_sync(0xffffffffu, sz, o);
    }
    __shared__ float ss[8][3];
    if (lane == 0) { ss[warp][0] = sx; ss[warp][1] = sy; ss[warp][2] = sz; }
    __syncthreads();
    if (warp == 0 && lane < 8) {
        sx = ss[lane][0]; sy = ss[lane][1]; sz = ss[lane][2];
        #pragma unroll
        for (int o = 4; o; o >>= 1) {
            sx += __shfl_down_sync(0x000000ffu, sx, o);
            sy += __shfl_down_sync(0x000000ffu, sy, o);
            sz += __shfl_down_sync(0x000000ffu, sz, o);
        }
        if (lane == 0) {
            const int idx = b * NTILE + tile;
            g_blocksum[idx * 3 + 0] = sx;
            g_blocksum[idx * 3 + 1] = sy;
            g_blocksum[idx * 3 + 2] = sz;
        }
    }
    __syncthreads();

    // ---- arrival protocol (threadfenceReduction pattern) ----
    __shared__ int s_islast;
    if (t == 0) {
        __threadfence();                      // publish this block's writes
        const int old = atomicAdd(&g_arrive[b], 1);
        s_islast = (old == NTILE - 1);
    }
    __syncthreads();
    if (!s_islast) return;
    if (t == 0) { g_arrive[b] = 0; __threadfence(); }  // reset for next graph replay

    // ================= last block of batch b: prefix + cnt + mean =================
    // 256 threads, 16 words each (4 x uint4)
    const uint4* mb4 = (const uint4*)(g_maskbits + (size_t)b * NWORDS);
    uint4 w4[4];
    #pragma unroll
    for (int i = 0; i < 4; ++i) w4[i] = mb4[t * 4 + i];

    int c[16];
    #pragma unroll
    for (int i = 0; i < 4; ++i) {
        c[i * 4 + 0] = __popc(w4[i].x); c[i * 4 + 1] = __popc(w4[i].y);
        c[i * 4 + 2] = __popc(w4[i].z); c[i * 4 + 3] = __popc(w4[i].w);
    }
    int lp[16]; int s = 0;
    #pragma unroll
    for (int i = 0; i < 16; ++i) { lp[i] = s; s += c[i]; }

    int inc = s;
    #pragma unroll
    for (int o = 1; o < 32; o <<= 1) {
        int v = __shfl_up_sync(0xffffffffu, inc, o);
        if (lane >= o) inc += v;
    }
    __shared__ int swarp[8], swpref[8], stot;
    if (lane == 31) swarp[warp] = inc;
    __syncthreads();
    if (warp == 0 && lane < 8) {
        int v = swarp[lane], winc = v;
        #pragma unroll
        for (int o = 1; o < 8; o <<= 1) {
            int u = __shfl_up_sync(0x000000ffu, winc, o);
            if (lane >= o) winc += u;
        }
        swpref[lane] = winc - v;
        if (lane == 7) stot = winc;
    }
    __syncthreads();

    const int off = swpref[warp] + (inc - s);
    int* __restrict__ pref = g_wordpref + (size_t)b * NWORDS + t * 16;
    #pragma unroll
    for (int i = 0; i < 16; ++i) pref[i] = off + lp[i];

    const int tot = stot;
    if (t == 0) g_cnt[b] = tot;

    if (warp == 0) {                          // mean from 64 per-tile partials
        const int i0 = (b * NTILE + lane) * 3;
        const int i1 = (b * NTILE + lane + 32) * 3;
        float mx = g_blocksum[i0 + 0] + g_blocksum[i1 + 0];
        float my = g_blocksum[i0 + 1] + g_blocksum[i1 + 1];
        float mz = g_blocksum[i0 + 2] + g_blocksum[i1 + 2];
        #pragma unroll
        for (int o = 16; o; o >>= 1) {
            mx += __shfl_down_sync(0xffffffffu, mx, o);
            my += __shfl_down_sync(0xffffffffu, my, o);
            mz += __shfl_down_sync(0xffffffffu, mz, o);
        }
        if (lane == 0) {
            const float d = fmaxf((float)tot, 1.0f);
            mx /= d; my /= d; mz /= d;
            g_mean[b * 3 + 0] = mx; g_mean[b * 3 + 1] = my; g_mean[b * 3 + 2] = mz;
            if (has_mean) {
                out_mean[b * 3 + 0] = mx;
                out_mean[b * 3 + 1] = my;
                out_mean[b * 3 + 2] = mz;
            }
        }
    }
}

// ---------------- Kernel 2: selection with smem-cached rank structure ----------------
// grid (2, BATCH) x 1024 threads: 128 blocks, one wave, search hits shared memory.
__global__ void __launch_bounds__(1024)
k_select(const float* __restrict__ pc, float* __restrict__ out) {
    const int b = blockIdx.y;
    const int t = threadIdx.x;
    const int j = blockIdx.x * 1024 + t;      // 0..MPTS-1
    const int slot = b * MPTS + j;

    __shared__ int      s_pref[NWORDS];       // 16 KB
    __shared__ unsigned s_word[NWORDS];       // 16 KB

    // stage this batch's rank structure (4 words per thread, coalesced uint4)
    {
        const uint4* sp = (const uint4*)(g_wordpref + (size_t)b * NWORDS);
        const uint4* sw = (const uint4*)(g_maskbits + (size_t)b * NWORDS);
        ((uint4*)s_pref)[t] = __ldg(&sp[t]);
        ((uint4*)s_word)[t] = __ldg(&sw[t]);
    }

    // independent loads before the barrier
    const int cnt = __ldg(&g_cnt[b]);
    const uint32_t higher = __ldg(&g_hi[slot]);
    const uint32_t lower  = __ldg(&g_lo[slot]);
    const float mx = __ldg(&g_mean[b * 3 + 0]);
    const float my = __ldg(&g_mean[b * 3 + 1]);
    const float mz = __ldg(&g_mean[b * 3 + 2]);

    __syncthreads();

    float* __restrict__ o = out + (size_t)slot * 3;

    if (cnt == 0) {                           // empty-mask override: batch id
        const float v = (float)b;
        o[0] = v; o[1] = v; o[2] = v;
        return;
    }

    const uint32_t span = (uint32_t)cnt;
    uint32_t mult = 65536u % span;
    mult = (mult * mult) % span;              // uint32 wraparound — matches lax semantics
    const int rnd = (int)(((higher % span) * mult + (lower % span)) % span);
    const int sel = (cnt <= MPTS && j < cnt) ? j : rnd;

    // binary search in smem: largest word w with pref[w] <= sel
    int lo = 0, hi = NWORDS, plo = 0;
    #pragma unroll
    for (int st = 0; st < 12; ++st) {         // 2^12 = 4096
        const int mid = (lo + hi) >> 1;
        const int v = s_pref[mid];
        const bool le = (v <= sel);
        lo  = le ? mid : lo;
        plo = le ? v   : plo;
        hi  = le ? hi  : mid;
    }
    unsigned w = s_word[lo];
    int r = sel - plo;                        // r-th set bit of w (0-based)

    int p = 0;
    {
        int cc = __popc(w & 0xFFFFu); if (r >= cc) { r -= cc; p += 16; w >>= 16; }
        cc = __popc(w & 0xFFu);       if (r >= cc) { r -= cc; p += 8;  w >>= 8;  }
        cc = __popc(w & 0xFu);        if (r >= cc) { r -= cc; p += 4;  w >>= 4;  }
        cc = __popc(w & 0x3u);        if (r >= cc) { r -= cc; p += 2;  w >>= 2;  }
        cc = (int)(w & 1u);           if (r >= cc) {          p += 1;            }
    }
    const int idx = lo * 32 + p;

    const float4 pt = __ldg((const float4*)pc + (size_t)b * NPTS + idx);
    o[0] = pt.x - mx;
    o[1] = pt.y - my;
    o[2] = pt.z - mz;
}

// ---------------- launch ----------------
extern "C" void kernel_launch(void* const* d_in, const int* in_sizes, int n_in,
                              void* d_out, int out_size) {
    const float* pc     = (const float*)d_in[0];
    const float* logits = (const float*)d_in[1];
    if (n_in >= 2 && in_sizes[0] == BATCH * 2 * NPTS && in_sizes[1] == BATCH * NPTS * 4) {
        pc     = (const float*)d_in[1];
        logits = (const float*)d_in[0];
    }
    float* out = (float*)d_out;

    // split(key(42)) — partitionable/foldlike: counters (0,0) and (0,1)
    uint32_t k1a, k1b, k2a, k2b;
    threefry2x32(0u, 42u, 0u, 0u, k1a, k1b);
    threefry2x32(0u, 42u, 0u, 1u, k2a, k2b);

    const size_t obj_elems = (size_t)BATCH * MPTS * 3;
    const int has_mean = (out_size >= (int)(obj_elems + BATCH * 3)) ? 1 : 0;

    k_mask_stats<<<dim3(NTILE, BATCH), 256>>>(pc, logits, k1a, k1b, k2a, k2b,
                                              out + obj_elems, has_mean);
    k_select    <<<dim3(MPTS / 1024, BATCH), 1024>>>(pc, out);
}